// round 13
// baseline (speedup 1.0000x reference)
#include <cuda_runtime.h>
#include <cuda_fp16.h>

#define NNODES 50000
#define NGRAPH 64
#define FIN    128
#define NCLS   10
#define MAXE   600000
#define NBLK   ((NNODES + 255) / 256)   // 196 scan blocks

// ---------------- scratch (static device arrays) -----------------------------
__device__ __half g_xlr1h[NNODES * 256]; // conv1 operand: [xl(128)|xr(128)] fp16
__device__ float  g_h1  [NNODES * 128];  // conv1 output (post-ELU), fp32
__device__ __half g_xlr2h[NNODES * 128]; // conv2 operand: [xl(64)|xr(64)] fp16
__device__ float  g_pool[NGRAPH * 64];
__device__ float  g_cnt [NGRAPH];
__device__ int    g_idx64;

__device__ int   g_deg     [NNODES];
__device__ int   g_rowstart[NNODES + 1];
__device__ int   g_cursor  [NNODES];
__device__ int   g_csr_src [MAXE];
__device__ int   g_bsum    [NBLK];
__device__ int   g_boff    [NBLK];

// ---------------- helpers -----------------------------------------------------
__device__ __forceinline__ void red_add4(float* p, float4 v) {
    asm volatile("red.global.add.v4.f32 [%0], {%1,%2,%3,%4};"
                 :: "l"(p), "f"(v.x), "f"(v.y), "f"(v.z), "f"(v.w) : "memory");
}
__device__ __forceinline__ float lrelu(float v) { return v > 0.f ? v : 0.2f * v; }
__device__ __forceinline__ float elu(float v)   { return v > 0.f ? v : expm1f(v); }

// widen a staged uint4 (8 fp16) to 8 floats
__device__ __forceinline__ void cvt8(uint4 r, float* f) {
    float2 a = __half22float2(*(const __half2*)&r.x);
    float2 b = __half22float2(*(const __half2*)&r.y);
    float2 c = __half22float2(*(const __half2*)&r.z);
    float2 d = __half22float2(*(const __half2*)&r.w);
    f[0] = a.x; f[1] = a.y; f[2] = b.x; f[3] = b.y;
    f[4] = c.x; f[5] = c.y; f[6] = d.x; f[7] = d.y;
}

// pack two floats into bf16x2 (first arg -> high half)
__device__ __forceinline__ unsigned packbf(float hi, float lo) {
    unsigned r;
    asm("cvt.rn.bf16x2.f32 %0, %1, %2;" : "=r"(r) : "f"(hi), "f"(lo));
    return r;
}
__device__ __forceinline__ void bfsplit2(float v0, float v1,
                                         unsigned& h, unsigned& l) {
    h = packbf(v1, v0);
    float h0 = __uint_as_float(h << 16);
    float h1 = __uint_as_float(h & 0xffff0000u);
    l = packbf(v1 - h1, v0 - h0);
}
__device__ __forceinline__ void mma_bf16(float* c, const unsigned* a,
                                         const unsigned* b) {
    asm volatile(
        "mma.sync.aligned.m16n8k16.row.col.f32.bf16.bf16.f32 "
        "{%0,%1,%2,%3}, {%4,%5,%6,%7}, {%8,%9}, {%0,%1,%2,%3};"
        : "+f"(c[0]), "+f"(c[1]), "+f"(c[2]), "+f"(c[3])
        : "r"(a[0]), "r"(a[1]), "r"(a[2]), "r"(a[3]), "r"(b[0]), "r"(b[1]));
}

// ---------------- dtype detection + zero (fused) ------------------------------
__global__ void init_kernel(const void* ei) {
    int i = blockIdx.x * blockDim.x + threadIdx.x;
    if (i == 0) {
        const long long* p = (const long long*)ei;
        int ok = 1;
        for (int k = 0; k < 16; k++) {
            long long v = p[k];
            if (v < 0 || v >= NNODES) ok = 0;
        }
        g_idx64 = ok;
    }
    if (i < NNODES)      g_deg[i] = 0;
    if (i < NGRAPH * 64) g_pool[i] = 0.f;
    if (i < NGRAPH)      g_cnt[i]  = 0.f;
}

// ---------------- CSR build ---------------------------------------------------
__global__ void hist_kernel(const void* __restrict__ ei, int E) {
    int e = blockIdx.x * blockDim.x + threadIdx.x;
    if (e >= E) return;
    int d = g_idx64 ? (int)((const long long*)ei)[E + e]
                    : ((const int*)ei)[E + e];
    atomicAdd(&g_deg[d], 1);
}

__global__ void scan1_kernel() {
    int i = blockIdx.x * 256 + threadIdx.x;
    int v = (i < NNODES) ? g_deg[i] : 0;
    int s = v;
    #pragma unroll
    for (int off = 16; off; off >>= 1) s += __shfl_xor_sync(~0u, s, off);
    __shared__ int ws[8];
    if ((threadIdx.x & 31) == 0) ws[threadIdx.x >> 5] = s;
    __syncthreads();
    if (threadIdx.x == 0) {
        int t = 0;
        #pragma unroll
        for (int w = 0; w < 8; w++) t += ws[w];
        g_bsum[blockIdx.x] = t;
    }
}

__global__ void scan2_kernel() {
    __shared__ int sh[256];
    int t = threadIdx.x;
    int v = (t < NBLK) ? g_bsum[t] : 0;
    sh[t] = v;
    __syncthreads();
    for (int off = 1; off < 256; off <<= 1) {
        int u = (t >= off) ? sh[t - off] : 0;
        __syncthreads();
        sh[t] += u;
        __syncthreads();
    }
    if (t < NBLK) g_boff[t] = sh[t] - v;
}

__global__ void scan3_kernel() {
    int i = blockIdx.x * 256 + threadIdx.x;
    int lane = threadIdx.x & 31, warp = threadIdx.x >> 5;
    int v = (i < NNODES) ? g_deg[i] : 0;
    int x = v;
    #pragma unroll
    for (int off = 1; off < 32; off <<= 1) {
        int y = __shfl_up_sync(~0u, x, off);
        if (lane >= off) x += y;
    }
    __shared__ int ws[8];
    if (lane == 31) ws[warp] = x;
    __syncthreads();
    if (threadIdx.x == 0) {
        int run = 0;
        #pragma unroll
        for (int w = 0; w < 8; w++) { int tmp = ws[w]; ws[w] = run; run += tmp; }
    }
    __syncthreads();
    int incl = x + ws[warp];
    int base = g_boff[blockIdx.x];
    if (i < NNODES) {
        int rs = base + incl - v;
        g_rowstart[i] = rs;
        g_cursor[i]   = rs;
        if (i == NNODES - 1) g_rowstart[NNODES] = base + incl;
    }
}

__global__ void scatter_kernel(const void* __restrict__ ei, int E) {
    int e = blockIdx.x * blockDim.x + threadIdx.x;
    if (e >= E) return;
    int s, d;
    if (g_idx64) {
        const long long* p = (const long long*)ei;
        s = (int)p[e]; d = (int)p[E + e];
    } else {
        const int* p = (const int*)ei;
        s = p[e]; d = p[E + e];
    }
    int pos = atomicAdd(&g_cursor[d], 1);
    g_csr_src[pos] = s;
}

// ---------------- tensor-core dual-weight GEMM (bf16 split, fp16 out) --------
#define AP 20
#define BP 20
__global__ __launch_bounds__(256) void gemm_tc(
        const float* __restrict__ A,
        const float* __restrict__ WL,
        const float* __restrict__ WR,
        __half* __restrict__ C,
        int M, int NHALF, int NN) {
    __shared__ unsigned AsH[128 * AP], AsL[128 * AP];
    __shared__ unsigned BsH[64 * BP],  BsL[64 * BP];

    const int t = threadIdx.x;
    const int lane = t & 31, g = lane >> 2, tig = lane & 3;
    const int w = t >> 5, wr = w & 3, wc = w >> 2;   // warp tile 32x32
    const int rowBase = blockIdx.y << 7;
    const int colTile = blockIdx.x << 6;

    const float* W;
    int colBase;
    if (colTile >= NHALF) { W = WR; colBase = colTile - NHALF; }
    else                  { W = WL; colBase = colTile; }

    float acc[2][4][4];
    #pragma unroll
    for (int mi = 0; mi < 2; mi++)
        #pragma unroll
        for (int ni = 0; ni < 4; ni++)
            #pragma unroll
            for (int j = 0; j < 4; j++) acc[mi][ni][j] = 0.f;

    const int arow = t >> 3, aj = t & 7;          // A: float4 per thread
    const int bcol = t & 63, bk2 = (t >> 6) << 2; // B: 4 k-pairs per col

    for (int k0 = 0; k0 < FIN; k0 += 32) {
        #pragma unroll
        for (int r = 0; r < 4; r++) {
            int row = arow + r * 32;
            int grow = rowBase + row;
            if (grow >= M) grow = M - 1;
            float4 v = *(const float4*)&A[(long)grow * FIN + k0 + (aj << 2)];
            unsigned h0, l0, h1, l1;
            bfsplit2(v.x, v.y, h0, l0);
            bfsplit2(v.z, v.w, h1, l1);
            int ad = row * AP + aj * 2;
            AsH[ad] = h0; AsH[ad + 1] = h1;
            AsL[ad] = l0; AsL[ad + 1] = l1;
        }
        {
            unsigned h[4], l[4];
            #pragma unroll
            for (int j = 0; j < 4; j++) {
                int krow = k0 + 2 * (bk2 + j);
                float v0 = W[(long)krow * NHALF + colBase + bcol];
                float v1 = W[(long)(krow + 1) * NHALF + colBase + bcol];
                bfsplit2(v0, v1, h[j], l[j]);
            }
            *(uint4*)&BsH[bcol * BP + bk2] = make_uint4(h[0], h[1], h[2], h[3]);
            *(uint4*)&BsL[bcol * BP + bk2] = make_uint4(l[0], l[1], l[2], l[3]);
        }
        __syncthreads();

        #pragma unroll
        for (int kk2 = 0; kk2 < 16; kk2 += 8) {   // two K=16 steps
            unsigned ah[2][4], al[2][4], bh[4][2], bl[4][2];
            #pragma unroll
            for (int mi = 0; mi < 2; mi++) {
                int rb  = (wr * 32 + mi * 16 + g) * AP;
                int rb8 = rb + 8 * AP;
                ah[mi][0] = AsH[rb  + kk2 + tig];
                ah[mi][1] = AsH[rb8 + kk2 + tig];
                ah[mi][2] = AsH[rb  + kk2 + 4 + tig];
                ah[mi][3] = AsH[rb8 + kk2 + 4 + tig];
                al[mi][0] = AsL[rb  + kk2 + tig];
                al[mi][1] = AsL[rb8 + kk2 + tig];
                al[mi][2] = AsL[rb  + kk2 + 4 + tig];
                al[mi][3] = AsL[rb8 + kk2 + 4 + tig];
            }
            #pragma unroll
            for (int ni = 0; ni < 4; ni++) {
                int cb = (wc * 32 + ni * 8 + g) * BP;
                bh[ni][0] = BsH[cb + kk2 + tig];
                bh[ni][1] = BsH[cb + kk2 + 4 + tig];
                bl[ni][0] = BsL[cb + kk2 + tig];
                bl[ni][1] = BsL[cb + kk2 + 4 + tig];
            }
            #pragma unroll
            for (int mi = 0; mi < 2; mi++)
                #pragma unroll
                for (int ni = 0; ni < 4; ni++) {
                    mma_bf16(acc[mi][ni], ah[mi], bh[ni]);
                    mma_bf16(acc[mi][ni], ah[mi], bl[ni]);
                    mma_bf16(acc[mi][ni], al[mi], bh[ni]);
                }
        }
        __syncthreads();
    }

    #pragma unroll
    for (int mi = 0; mi < 2; mi++) {
        int row0 = rowBase + wr * 32 + mi * 16 + g;
        #pragma unroll
        for (int ni = 0; ni < 4; ni++) {
            int col = colTile + wc * 32 + ni * 8 + 2 * tig;
            if (row0 < M)
                *(__half2*)&C[(long)row0 * NN + col] =
                    __floats2half2_rn(acc[mi][ni][0], acc[mi][ni][1]);
            if (row0 + 8 < M)
                *(__half2*)&C[(long)(row0 + 8) * NN + col] =
                    __floats2half2_rn(acc[mi][ni][2], acc[mi][ni][3]);
        }
    }
}

// ---------------- conv1: 16 lanes/node, 2 nodes/warp, unroll-4 MLP -----------
__global__ void conv1_kernel(const float* __restrict__ b1,
                             const float* __restrict__ att) {
    int n = (blockIdx.x * blockDim.x + threadIdx.x) >> 4;
    int l = threadIdx.x & 15;
    int c8 = l << 3;

    float av[8], xr[8], bb[8], acc[8];
    *(float4*)&av[0] = *(const float4*)&att[c8];
    *(float4*)&av[4] = *(const float4*)&att[c8 + 4];
    *(float4*)&bb[0] = *(const float4*)&b1[c8];
    *(float4*)&bb[4] = *(const float4*)&b1[c8 + 4];
    cvt8(*(const uint4*)&g_xlr1h[(long)n * 256 + 128 + c8], xr);
    #pragma unroll
    for (int j = 0; j < 8; j++) acc[j] = 0.f;
    float den = 0.f;

    int rs = g_rowstart[n], re = g_rowstart[n + 1];
    int cnt = re - rs + 1;                        // edge 0 = self loop
    int mcnt = max(cnt, __shfl_xor_sync(~0u, cnt, 16));

    for (int i = 0; i < mcnt; i += 4) {
        bool v0 = i < cnt, v1 = i + 1 < cnt, v2 = i + 2 < cnt, v3 = i + 3 < cnt;
        // all 4 indices first, then all 4 row gathers -> MLP 4 per subgroup
        int s0 = (i == 0) ? n : (v0 ? g_csr_src[rs + i - 1] : n);
        int s1 = v1 ? g_csr_src[rs + i]     : n;
        int s2 = v2 ? g_csr_src[rs + i + 1] : n;
        int s3 = v3 ? g_csr_src[rs + i + 2] : n;
        uint4 r0 = *(const uint4*)&g_xlr1h[(long)s0 * 256 + c8];
        uint4 r1 = *(const uint4*)&g_xlr1h[(long)s1 * 256 + c8];
        uint4 r2 = *(const uint4*)&g_xlr1h[(long)s2 * 256 + c8];
        uint4 r3 = *(const uint4*)&g_xlr1h[(long)s3 * 256 + c8];
        float a0[8], a1[8], a2[8], a3[8];
        cvt8(r0, a0); cvt8(r1, a1); cvt8(r2, a2); cvt8(r3, a3);

        float e0 = 0.f, e1 = 0.f, e2 = 0.f, e3 = 0.f;
        #pragma unroll
        for (int j = 0; j < 8; j++) {
            e0 += lrelu(a0[j] + xr[j]) * av[j];
            e1 += lrelu(a1[j] + xr[j]) * av[j];
            e2 += lrelu(a2[j] + xr[j]) * av[j];
            e3 += lrelu(a3[j] + xr[j]) * av[j];
        }
        #pragma unroll
        for (int off = 4; off; off >>= 1) {       // head group = 8 lanes
            e0 += __shfl_xor_sync(~0u, e0, off);
            e1 += __shfl_xor_sync(~0u, e1, off);
            e2 += __shfl_xor_sync(~0u, e2, off);
            e3 += __shfl_xor_sync(~0u, e3, off);
        }
        float p0 = v0 ? __expf(e0) : 0.f;
        float p1 = v1 ? __expf(e1) : 0.f;
        float p2 = v2 ? __expf(e2) : 0.f;
        float p3 = v3 ? __expf(e3) : 0.f;
        #pragma unroll
        for (int j = 0; j < 8; j++)
            acc[j] += p0 * a0[j] + p1 * a1[j] + p2 * a2[j] + p3 * a3[j];
        den += p0 + p1 + p2 + p3;
    }
    float inv = 1.f / den;
    float h[8];
    #pragma unroll
    for (int j = 0; j < 8; j++) h[j] = elu(acc[j] * inv + bb[j]);
    *(float4*)&g_h1[(long)n * 128 + c8]     = *(float4*)&h[0];
    *(float4*)&g_h1[(long)n * 128 + c8 + 4] = *(float4*)&h[4];
}

// ---------------- conv2: 8 lanes/node, 4 nodes/warp, unroll-4 MLP ------------
__global__ void conv2_kernel(const float* __restrict__ b2,
                             const float* __restrict__ att,
                             const void* __restrict__ batch) {
    int n = (blockIdx.x * blockDim.x + threadIdx.x) >> 3;
    if (n >= NNODES) return;
    int l = threadIdx.x & 7;
    int c8 = l << 3;

    float av[8], xr[8], bb[8], acc[8];
    *(float4*)&av[0] = *(const float4*)&att[c8];
    *(float4*)&av[4] = *(const float4*)&att[c8 + 4];
    *(float4*)&bb[0] = *(const float4*)&b2[c8];
    *(float4*)&bb[4] = *(const float4*)&b2[c8 + 4];
    cvt8(*(const uint4*)&g_xlr2h[(long)n * 128 + 64 + c8], xr);
    #pragma unroll
    for (int j = 0; j < 8; j++) acc[j] = 0.f;
    float den = 0.f;

    int rs = g_rowstart[n], re = g_rowstart[n + 1];
    int cnt = re - rs + 1;
    int mcnt = max(cnt, __shfl_xor_sync(~0u, cnt, 8));
    mcnt = max(mcnt, __shfl_xor_sync(~0u, mcnt, 16));

    for (int i = 0; i < mcnt; i += 4) {
        bool v0 = i < cnt, v1 = i + 1 < cnt, v2 = i + 2 < cnt, v3 = i + 3 < cnt;
        int s0 = (i == 0) ? n : (v0 ? g_csr_src[rs + i - 1] : n);
        int s1 = v1 ? g_csr_src[rs + i]     : n;
        int s2 = v2 ? g_csr_src[rs + i + 1] : n;
        int s3 = v3 ? g_csr_src[rs + i + 2] : n;
        uint4 r0 = *(const uint4*)&g_xlr2h[(long)s0 * 128 + c8];
        uint4 r1 = *(const uint4*)&g_xlr2h[(long)s1 * 128 + c8];
        uint4 r2 = *(const uint4*)&g_xlr2h[(long)s2 * 128 + c8];
        uint4 r3 = *(const uint4*)&g_xlr2h[(long)s3 * 128 + c8];
        float a0[8], a1[8], a2[8], a3[8];
        cvt8(r0, a0); cvt8(r1, a1); cvt8(r2, a2); cvt8(r3, a3);

        float e0 = 0.f, e1 = 0.f, e2 = 0.f, e3 = 0.f;
        #pragma unroll
        for (int j = 0; j < 8; j++) {
            e0 += lrelu(a0[j] + xr[j]) * av[j];
            e1 += lrelu(a1[j] + xr[j]) * av[j];
            e2 += lrelu(a2[j] + xr[j]) * av[j];
            e3 += lrelu(a3[j] + xr[j]) * av[j];
        }
        #pragma unroll
        for (int off = 4; off; off >>= 1) {       // node group = 8 lanes
            e0 += __shfl_xor_sync(~0u, e0, off);
            e1 += __shfl_xor_sync(~0u, e1, off);
            e2 += __shfl_xor_sync(~0u, e2, off);
            e3 += __shfl_xor_sync(~0u, e3, off);
        }
        float p0 = v0 ? __expf(e0) : 0.f;
        float p1 = v1 ? __expf(e1) : 0.f;
        float p2 = v2 ? __expf(e2) : 0.f;
        float p3 = v3 ? __expf(e3) : 0.f;
        #pragma unroll
        for (int j = 0; j < 8; j++)
            acc[j] += p0 * a0[j] + p1 * a1[j] + p2 * a2[j] + p3 * a3[j];
        den += p0 + p1 + p2 + p3;
    }
    float inv = 1.f / den;
    float h[8];
    #pragma unroll
    for (int j = 0; j < 8; j++) h[j] = elu(acc[j] * inv + bb[j]);

    int gph = g_idx64 ? (int)((const long long*)batch)[n]
                      : ((const int*)batch)[n];
    red_add4(&g_pool[gph * 64 + c8],     *(float4*)&h[0]);
    red_add4(&g_pool[gph * 64 + c8 + 4], *(float4*)&h[4]);
    if (l == 0) atomicAdd(&g_cnt[gph], 1.0f);
}

// ---------------- final: out = (pool/cnt) @ Wlin + blin ----------------------
__global__ void final_kernel(const float* __restrict__ Wlin,
                             const float* __restrict__ blin,
                             float* __restrict__ out) {
    int t = threadIdx.x;
    if (t >= NGRAPH * NCLS) return;
    int g = t / NCLS, j = t - g * NCLS;
    float inv = 1.f / fmaxf(g_cnt[g], 1.f);
    float s = 0.f;
    #pragma unroll
    for (int c = 0; c < 64; c++) s += g_pool[g * 64 + c] * Wlin[c * NCLS + j];
    out[t] = s * inv + blin[j];
}

// ---------------- launch ------------------------------------------------------
extern "C" void kernel_launch(void* const* d_in, const int* in_sizes, int n_in,
                              void* d_out, int out_size) {
    const float* x    = (const float*)d_in[0];
    const void*  ei   = d_in[1];
    const void*  bat  = d_in[2];
    const float* Wl1  = (const float*)d_in[3];
    const float* Wr1  = (const float*)d_in[4];
    const float* att1 = (const float*)d_in[5];
    const float* b1   = (const float*)d_in[6];
    const float* Wl2  = (const float*)d_in[7];
    const float* Wr2  = (const float*)d_in[8];
    const float* att2 = (const float*)d_in[9];
    const float* b2   = (const float*)d_in[10];
    const float* Wlin = (const float*)d_in[11];
    const float* blin = (const float*)d_in[12];
    float* out = (float*)d_out;

    int Nn = in_sizes[0] / 128;   // 50000
    int E  = in_sizes[1] / 2;     // 600000

    __half *p_xlr1, *p_xlr2;
    float *p_h1;
    cudaGetSymbolAddress((void**)&p_xlr1, g_xlr1h);
    cudaGetSymbolAddress((void**)&p_xlr2, g_xlr2h);
    cudaGetSymbolAddress((void**)&p_h1,   g_h1);

    // side stream + events, created once (host-side objects; no device mem)
    static cudaStream_t s1 = nullptr;
    static cudaEvent_t evFork = nullptr, evJoin = nullptr;
    if (s1 == nullptr) {
        cudaStreamCreateWithFlags(&s1, cudaStreamNonBlocking);
        cudaEventCreateWithFlags(&evFork, cudaEventDisableTiming);
        cudaEventCreateWithFlags(&evJoin, cudaEventDisableTiming);
    }

    // ---- fork: gemm1 on s1, CSR build on main stream, concurrently ----
    cudaEventRecord(evFork, 0);
    cudaStreamWaitEvent(s1, evFork, 0);

    dim3 g1(4, (Nn + 127) / 128);
    gemm_tc<<<g1, 256, 0, s1>>>(x, Wl1, Wr1, p_xlr1, Nn, 128, 256);
    cudaEventRecord(evJoin, s1);

    init_kernel<<<(Nn + 255) / 256, 256>>>(ei);
    hist_kernel<<<(E + 255) / 256, 256>>>(ei, E);
    scan1_kernel<<<NBLK, 256>>>();
    scan2_kernel<<<1, 256>>>();
    scan3_kernel<<<NBLK, 256>>>();
    scatter_kernel<<<(E + 255) / 256, 256>>>(ei, E);

    // ---- join: conv1 needs both gemm1 and the CSR ----
    cudaStreamWaitEvent(0, evJoin, 0);

    conv1_kernel<<<(Nn * 16 + 255) / 256, 256>>>(b1, att1);

    dim3 g2(2, (Nn + 127) / 128);
    gemm_tc<<<g2, 256>>>(p_h1, Wl2, Wr2, p_xlr2, Nn, 64, 128);
    conv2_kernel<<<(Nn * 8 + 255) / 256, 256>>>(b2, att2, bat);

    final_kernel<<<1, 640>>>(Wlin, blin, out);
}

// round 14
// speedup vs baseline: 1.1776x; 1.1776x over previous
#include <cuda_runtime.h>
#include <cuda_fp16.h>

#define NNODES 50000
#define NGRAPH 64
#define FIN    128
#define NCLS   10
#define MAXE   600000
#define NBLK   ((NNODES + 255) / 256)   // 196 scan blocks

// ---------------- scratch (static device arrays) -----------------------------
__device__ __half g_xlr1h[NNODES * 256]; // conv1 operand: [xl(128)|xr(128)] fp16
__device__ float  g_h1  [NNODES * 128];  // conv1 output (post-ELU), fp32
__device__ __half g_xlr2h[NNODES * 128]; // conv2 operand: [xl(64)|xr(64)] fp16
__device__ float  g_pool[NGRAPH * 64];
__device__ float  g_cnt [NGRAPH];
__device__ int    g_idx64;

__device__ int   g_deg     [NNODES];
__device__ int   g_rowstart[NNODES + 1];
__device__ int   g_cursor  [NNODES];
__device__ int   g_csr_src [MAXE];
__device__ int   g_bsum    [NBLK];
__device__ int   g_boff    [NBLK];

// ---------------- helpers -----------------------------------------------------
__device__ __forceinline__ void red_add4(float* p, float4 v) {
    asm volatile("red.global.add.v4.f32 [%0], {%1,%2,%3,%4};"
                 :: "l"(p), "f"(v.x), "f"(v.y), "f"(v.z), "f"(v.w) : "memory");
}
__device__ __forceinline__ float lrelu(float v) { return v > 0.f ? v : 0.2f * v; }
__device__ __forceinline__ float elu(float v)   { return v > 0.f ? v : expm1f(v); }

// load 8 consecutive fp16 channels (16B) and widen to 8 floats
__device__ __forceinline__ void ldh8(const __half* p, float* f) {
    uint4 r = *(const uint4*)p;
    float2 a = __half22float2(*(const __half2*)&r.x);
    float2 b = __half22float2(*(const __half2*)&r.y);
    float2 c = __half22float2(*(const __half2*)&r.z);
    float2 d = __half22float2(*(const __half2*)&r.w);
    f[0] = a.x; f[1] = a.y; f[2] = b.x; f[3] = b.y;
    f[4] = c.x; f[5] = c.y; f[6] = d.x; f[7] = d.y;
}

// pack two floats into bf16x2 (first arg -> high half)
__device__ __forceinline__ unsigned packbf(float hi, float lo) {
    unsigned r;
    asm("cvt.rn.bf16x2.f32 %0, %1, %2;" : "=r"(r) : "f"(hi), "f"(lo));
    return r;
}
__device__ __forceinline__ void bfsplit2(float v0, float v1,
                                         unsigned& h, unsigned& l) {
    h = packbf(v1, v0);
    float h0 = __uint_as_float(h << 16);
    float h1 = __uint_as_float(h & 0xffff0000u);
    l = packbf(v1 - h1, v0 - h0);
}
__device__ __forceinline__ void mma_bf16(float* c, const unsigned* a,
                                         const unsigned* b) {
    asm volatile(
        "mma.sync.aligned.m16n8k16.row.col.f32.bf16.bf16.f32 "
        "{%0,%1,%2,%3}, {%4,%5,%6,%7}, {%8,%9}, {%0,%1,%2,%3};"
        : "+f"(c[0]), "+f"(c[1]), "+f"(c[2]), "+f"(c[3])
        : "r"(a[0]), "r"(a[1]), "r"(a[2]), "r"(a[3]), "r"(b[0]), "r"(b[1]));
}

// ---------------- dtype detection + zero (fused) ------------------------------
__global__ void init_kernel(const void* ei) {
    int i = blockIdx.x * blockDim.x + threadIdx.x;
    if (i == 0) {
        const long long* p = (const long long*)ei;
        int ok = 1;
        for (int k = 0; k < 16; k++) {
            long long v = p[k];
            if (v < 0 || v >= NNODES) ok = 0;
        }
        g_idx64 = ok;
    }
    if (i < NNODES)      g_deg[i] = 0;
    if (i < NGRAPH * 64) g_pool[i] = 0.f;
    if (i < NGRAPH)      g_cnt[i]  = 0.f;
}

// ---------------- CSR build ---------------------------------------------------
__global__ void hist_kernel(const void* __restrict__ ei, int E) {
    int e = blockIdx.x * blockDim.x + threadIdx.x;
    if (e >= E) return;
    int d = g_idx64 ? (int)((const long long*)ei)[E + e]
                    : ((const int*)ei)[E + e];
    atomicAdd(&g_deg[d], 1);
}

__global__ void scan1_kernel() {
    int i = blockIdx.x * 256 + threadIdx.x;
    int v = (i < NNODES) ? g_deg[i] : 0;
    int s = v;
    #pragma unroll
    for (int off = 16; off; off >>= 1) s += __shfl_xor_sync(~0u, s, off);
    __shared__ int ws[8];
    if ((threadIdx.x & 31) == 0) ws[threadIdx.x >> 5] = s;
    __syncthreads();
    if (threadIdx.x == 0) {
        int t = 0;
        #pragma unroll
        for (int w = 0; w < 8; w++) t += ws[w];
        g_bsum[blockIdx.x] = t;
    }
}

__global__ void scan2_kernel() {
    __shared__ int sh[256];
    int t = threadIdx.x;
    int v = (t < NBLK) ? g_bsum[t] : 0;
    sh[t] = v;
    __syncthreads();
    for (int off = 1; off < 256; off <<= 1) {
        int u = (t >= off) ? sh[t - off] : 0;
        __syncthreads();
        sh[t] += u;
        __syncthreads();
    }
    if (t < NBLK) g_boff[t] = sh[t] - v;
}

__global__ void scan3_kernel() {
    int i = blockIdx.x * 256 + threadIdx.x;
    int lane = threadIdx.x & 31, warp = threadIdx.x >> 5;
    int v = (i < NNODES) ? g_deg[i] : 0;
    int x = v;
    #pragma unroll
    for (int off = 1; off < 32; off <<= 1) {
        int y = __shfl_up_sync(~0u, x, off);
        if (lane >= off) x += y;
    }
    __shared__ int ws[8];
    if (lane == 31) ws[warp] = x;
    __syncthreads();
    if (threadIdx.x == 0) {
        int run = 0;
        #pragma unroll
        for (int w = 0; w < 8; w++) { int tmp = ws[w]; ws[w] = run; run += tmp; }
    }
    __syncthreads();
    int incl = x + ws[warp];
    int base = g_boff[blockIdx.x];
    if (i < NNODES) {
        int rs = base + incl - v;
        g_rowstart[i] = rs;
        g_cursor[i]   = rs;
        if (i == NNODES - 1) g_rowstart[NNODES] = base + incl;
    }
}

__global__ void scatter_kernel(const void* __restrict__ ei, int E) {
    int e = blockIdx.x * blockDim.x + threadIdx.x;
    if (e >= E) return;
    int s, d;
    if (g_idx64) {
        const long long* p = (const long long*)ei;
        s = (int)p[e]; d = (int)p[E + e];
    } else {
        const int* p = (const int*)ei;
        s = p[e]; d = p[E + e];
    }
    int pos = atomicAdd(&g_cursor[d], 1);
    g_csr_src[pos] = s;
}

// ---------------- tensor-core dual-weight GEMM (bf16 split, prefetch) --------
#define AP 20
#define BP 20
__global__ __launch_bounds__(256) void gemm_tc(
        const float* __restrict__ A,
        const float* __restrict__ WL,
        const float* __restrict__ WR,
        __half* __restrict__ C,
        int M, int NHALF, int NN) {
    __shared__ unsigned AsH[128 * AP], AsL[128 * AP];
    __shared__ unsigned BsH[64 * BP],  BsL[64 * BP];

    const int t = threadIdx.x;
    const int lane = t & 31, g = lane >> 2, tig = lane & 3;
    const int w = t >> 5, wr = w & 3, wc = w >> 2;   // warp tile 32x32
    const int rowBase = blockIdx.y << 7;
    const int colTile = blockIdx.x << 6;

    const float* W;
    int colBase;
    if (colTile >= NHALF) { W = WR; colBase = colTile - NHALF; }
    else                  { W = WL; colBase = colTile; }

    float acc[2][4][4];
    #pragma unroll
    for (int mi = 0; mi < 2; mi++)
        #pragma unroll
        for (int ni = 0; ni < 4; ni++)
            #pragma unroll
            for (int j = 0; j < 4; j++) acc[mi][ni][j] = 0.f;

    const int arow = t >> 3, aj = t & 7;          // A: float4 per thread
    const int bcol = t & 63, bk2 = (t >> 6) << 2; // B: 4 k-pairs per col

    // prefetch k0 = 0 into registers
    float4 pa[4];
    float  pb[8];
    #pragma unroll
    for (int r = 0; r < 4; r++) {
        int grow = rowBase + arow + r * 32;
        if (grow >= M) grow = M - 1;
        pa[r] = *(const float4*)&A[(long)grow * FIN + (aj << 2)];
    }
    #pragma unroll
    for (int j = 0; j < 4; j++) {
        int krow = 2 * (bk2 + j);
        pb[2 * j]     = W[(long)krow * NHALF + colBase + bcol];
        pb[2 * j + 1] = W[(long)(krow + 1) * NHALF + colBase + bcol];
    }

    for (int k0 = 0; k0 < FIN; k0 += 32) {
        // split & store the prefetched tile
        #pragma unroll
        for (int r = 0; r < 4; r++) {
            unsigned h0, l0, h1, l1;
            bfsplit2(pa[r].x, pa[r].y, h0, l0);
            bfsplit2(pa[r].z, pa[r].w, h1, l1);
            int ad = (arow + r * 32) * AP + aj * 2;
            AsH[ad] = h0; AsH[ad + 1] = h1;
            AsL[ad] = l0; AsL[ad + 1] = l1;
        }
        {
            unsigned h[4], l[4];
            #pragma unroll
            for (int j = 0; j < 4; j++)
                bfsplit2(pb[2 * j], pb[2 * j + 1], h[j], l[j]);
            *(uint4*)&BsH[bcol * BP + bk2] = make_uint4(h[0], h[1], h[2], h[3]);
            *(uint4*)&BsL[bcol * BP + bk2] = make_uint4(l[0], l[1], l[2], l[3]);
        }
        __syncthreads();

        // prefetch next k0 while tensor cores work on this one
        if (k0 + 32 < FIN) {
            #pragma unroll
            for (int r = 0; r < 4; r++) {
                int grow = rowBase + arow + r * 32;
                if (grow >= M) grow = M - 1;
                pa[r] = *(const float4*)&A[(long)grow * FIN + k0 + 32 + (aj << 2)];
            }
            #pragma unroll
            for (int j = 0; j < 4; j++) {
                int krow = k0 + 32 + 2 * (bk2 + j);
                pb[2 * j]     = W[(long)krow * NHALF + colBase + bcol];
                pb[2 * j + 1] = W[(long)(krow + 1) * NHALF + colBase + bcol];
            }
        }

        #pragma unroll
        for (int kk2 = 0; kk2 < 16; kk2 += 8) {   // two K=16 steps
            unsigned ah[2][4], al[2][4], bh[4][2], bl[4][2];
            #pragma unroll
            for (int mi = 0; mi < 2; mi++) {
                int rb  = (wr * 32 + mi * 16 + g) * AP;
                int rb8 = rb + 8 * AP;
                ah[mi][0] = AsH[rb  + kk2 + tig];
                ah[mi][1] = AsH[rb8 + kk2 + tig];
                ah[mi][2] = AsH[rb  + kk2 + 4 + tig];
                ah[mi][3] = AsH[rb8 + kk2 + 4 + tig];
                al[mi][0] = AsL[rb  + kk2 + tig];
                al[mi][1] = AsL[rb8 + kk2 + tig];
                al[mi][2] = AsL[rb  + kk2 + 4 + tig];
                al[mi][3] = AsL[rb8 + kk2 + 4 + tig];
            }
            #pragma unroll
            for (int ni = 0; ni < 4; ni++) {
                int cb = (wc * 32 + ni * 8 + g) * BP;
                bh[ni][0] = BsH[cb + kk2 + tig];
                bh[ni][1] = BsH[cb + kk2 + 4 + tig];
                bl[ni][0] = BsL[cb + kk2 + tig];
                bl[ni][1] = BsL[cb + kk2 + 4 + tig];
            }
            #pragma unroll
            for (int mi = 0; mi < 2; mi++)
                #pragma unroll
                for (int ni = 0; ni < 4; ni++) {
                    mma_bf16(acc[mi][ni], ah[mi], bh[ni]);
                    mma_bf16(acc[mi][ni], ah[mi], bl[ni]);
                    mma_bf16(acc[mi][ni], al[mi], bh[ni]);
                }
        }
        __syncthreads();
    }

    #pragma unroll
    for (int mi = 0; mi < 2; mi++) {
        int row0 = rowBase + wr * 32 + mi * 16 + g;
        #pragma unroll
        for (int ni = 0; ni < 4; ni++) {
            int col = colTile + wc * 32 + ni * 8 + 2 * tig;
            if (row0 < M)
                *(__half2*)&C[(long)row0 * NN + col] =
                    __floats2half2_rn(acc[mi][ni][0], acc[mi][ni][1]);
            if (row0 + 8 < M)
                *(__half2*)&C[(long)(row0 + 8) * NN + col] =
                    __floats2half2_rn(acc[mi][ni][2], acc[mi][ni][3]);
        }
    }
}

// ---------------- conv1: 16 lanes/node (8 ch/lane), 2 nodes/warp, unroll-2 ---
__global__ void conv1_kernel(const float* __restrict__ b1,
                             const float* __restrict__ att) {
    int n = (blockIdx.x * blockDim.x + threadIdx.x) >> 4;   // node (2 per warp)
    int l = threadIdx.x & 15;                               // lane in node group
    int c8 = l << 3;                                        // channel base

    float av[8], xr[8], bb[8], acc[8];
    *(float4*)&av[0] = *(const float4*)&att[c8];
    *(float4*)&av[4] = *(const float4*)&att[c8 + 4];
    *(float4*)&bb[0] = *(const float4*)&b1[c8];
    *(float4*)&bb[4] = *(const float4*)&b1[c8 + 4];
    ldh8(&g_xlr1h[(long)n * 256 + 128 + c8], xr);
    #pragma unroll
    for (int j = 0; j < 8; j++) acc[j] = 0.f;
    float den = 0.f;

    int rs = g_rowstart[n], re = g_rowstart[n + 1];
    int cnt = re - rs + 1;                        // edge 0 = self loop
    int mcnt = max(cnt, __shfl_xor_sync(~0u, cnt, 16));

    for (int i = 0; i < mcnt; i += 2) {
        bool v0 = i < cnt, v1 = i + 1 < cnt;
        int s0 = (i == 0) ? n : (v0 ? g_csr_src[rs + i - 1] : n);
        int s1 = v1 ? g_csr_src[rs + i] : n;
        float a0[8], a1[8];
        ldh8(&g_xlr1h[(long)s0 * 256 + c8], a0);
        ldh8(&g_xlr1h[(long)s1 * 256 + c8], a1);

        float e0 = 0.f, e1 = 0.f;
        #pragma unroll
        for (int j = 0; j < 8; j++) {
            e0 += lrelu(a0[j] + xr[j]) * av[j];
            e1 += lrelu(a1[j] + xr[j]) * av[j];
        }
        #pragma unroll
        for (int off = 4; off; off >>= 1) {       // head group = 8 lanes
            e0 += __shfl_xor_sync(~0u, e0, off);
            e1 += __shfl_xor_sync(~0u, e1, off);
        }
        float p0 = v0 ? __expf(e0) : 0.f;
        float p1 = v1 ? __expf(e1) : 0.f;
        #pragma unroll
        for (int j = 0; j < 8; j++) acc[j] += p0 * a0[j] + p1 * a1[j];
        den += p0 + p1;
    }
    float inv = 1.f / den;
    float h[8];
    #pragma unroll
    for (int j = 0; j < 8; j++) h[j] = elu(acc[j] * inv + bb[j]);
    *(float4*)&g_h1[(long)n * 128 + c8]     = *(float4*)&h[0];
    *(float4*)&g_h1[(long)n * 128 + c8 + 4] = *(float4*)&h[4];
}

// ---------------- conv2: 8 lanes/node (8 ch/lane), 4 nodes/warp, unroll-2 ----
__global__ void conv2_kernel(const float* __restrict__ b2,
                             const float* __restrict__ att,
                             const void* __restrict__ batch) {
    int n = (blockIdx.x * blockDim.x + threadIdx.x) >> 3;
    if (n >= NNODES) return;
    int l = threadIdx.x & 7;
    int c8 = l << 3;

    float av[8], xr[8], bb[8], acc[8];
    *(float4*)&av[0] = *(const float4*)&att[c8];
    *(float4*)&av[4] = *(const float4*)&att[c8 + 4];
    *(float4*)&bb[0] = *(const float4*)&b2[c8];
    *(float4*)&bb[4] = *(const float4*)&b2[c8 + 4];
    ldh8(&g_xlr2h[(long)n * 128 + 64 + c8], xr);
    #pragma unroll
    for (int j = 0; j < 8; j++) acc[j] = 0.f;
    float den = 0.f;

    int rs = g_rowstart[n], re = g_rowstart[n + 1];
    int cnt = re - rs + 1;
    int mcnt = max(cnt, __shfl_xor_sync(~0u, cnt, 8));
    mcnt = max(mcnt, __shfl_xor_sync(~0u, mcnt, 16));

    for (int i = 0; i < mcnt; i += 2) {
        bool v0 = i < cnt, v1 = i + 1 < cnt;
        int s0 = (i == 0) ? n : (v0 ? g_csr_src[rs + i - 1] : n);
        int s1 = v1 ? g_csr_src[rs + i] : n;
        float a0[8], a1[8];
        ldh8(&g_xlr2h[(long)s0 * 128 + c8], a0);
        ldh8(&g_xlr2h[(long)s1 * 128 + c8], a1);

        float e0 = 0.f, e1 = 0.f;
        #pragma unroll
        for (int j = 0; j < 8; j++) {
            e0 += lrelu(a0[j] + xr[j]) * av[j];
            e1 += lrelu(a1[j] + xr[j]) * av[j];
        }
        #pragma unroll
        for (int off = 4; off; off >>= 1) {       // node group = 8 lanes
            e0 += __shfl_xor_sync(~0u, e0, off);
            e1 += __shfl_xor_sync(~0u, e1, off);
        }
        float p0 = v0 ? __expf(e0) : 0.f;
        float p1 = v1 ? __expf(e1) : 0.f;
        #pragma unroll
        for (int j = 0; j < 8; j++) acc[j] += p0 * a0[j] + p1 * a1[j];
        den += p0 + p1;
    }
    float inv = 1.f / den;
    float h[8];
    #pragma unroll
    for (int j = 0; j < 8; j++) h[j] = elu(acc[j] * inv + bb[j]);

    int gph = g_idx64 ? (int)((const long long*)batch)[n]
                      : ((const int*)batch)[n];
    red_add4(&g_pool[gph * 64 + c8],     *(float4*)&h[0]);
    red_add4(&g_pool[gph * 64 + c8 + 4], *(float4*)&h[4]);
    if (l == 0) atomicAdd(&g_cnt[gph], 1.0f);
}

// ---------------- final: out = (pool/cnt) @ Wlin + blin ----------------------
__global__ void final_kernel(const float* __restrict__ Wlin,
                             const float* __restrict__ blin,
                             float* __restrict__ out) {
    int t = threadIdx.x;
    if (t >= NGRAPH * NCLS) return;
    int g = t / NCLS, j = t - g * NCLS;
    float inv = 1.f / fmaxf(g_cnt[g], 1.f);
    float s = 0.f;
    #pragma unroll
    for (int c = 0; c < 64; c++) s += g_pool[g * 64 + c] * Wlin[c * NCLS + j];
    out[t] = s * inv + blin[j];
}

// ---------------- launch ------------------------------------------------------
extern "C" void kernel_launch(void* const* d_in, const int* in_sizes, int n_in,
                              void* d_out, int out_size) {
    const float* x    = (const float*)d_in[0];
    const void*  ei   = d_in[1];
    const void*  bat  = d_in[2];
    const float* Wl1  = (const float*)d_in[3];
    const float* Wr1  = (const float*)d_in[4];
    const float* att1 = (const float*)d_in[5];
    const float* b1   = (const float*)d_in[6];
    const float* Wl2  = (const float*)d_in[7];
    const float* Wr2  = (const float*)d_in[8];
    const float* att2 = (const float*)d_in[9];
    const float* b2   = (const float*)d_in[10];
    const float* Wlin = (const float*)d_in[11];
    const float* blin = (const float*)d_in[12];
    float* out = (float*)d_out;

    int Nn = in_sizes[0] / 128;   // 50000
    int E  = in_sizes[1] / 2;     // 600000

    __half *p_xlr1, *p_xlr2;
    float *p_h1;
    cudaGetSymbolAddress((void**)&p_xlr1, g_xlr1h);
    cudaGetSymbolAddress((void**)&p_xlr2, g_xlr2h);
    cudaGetSymbolAddress((void**)&p_h1,   g_h1);

    // side stream + events, created once (host-side objects; no device mem)
    static cudaStream_t s1 = nullptr;
    static cudaEvent_t evFork = nullptr, evJoin = nullptr;
    if (s1 == nullptr) {
        cudaStreamCreateWithFlags(&s1, cudaStreamNonBlocking);
        cudaEventCreateWithFlags(&evFork, cudaEventDisableTiming);
        cudaEventCreateWithFlags(&evJoin, cudaEventDisableTiming);
    }

    // ---- fork: gemm1 on s1, CSR build on main stream, concurrently ----
    cudaEventRecord(evFork, 0);
    cudaStreamWaitEvent(s1, evFork, 0);

    dim3 g1(4, (Nn + 127) / 128);
    gemm_tc<<<g1, 256, 0, s1>>>(x, Wl1, Wr1, p_xlr1, Nn, 128, 256);
    cudaEventRecord(evJoin, s1);

    init_kernel<<<(Nn + 255) / 256, 256>>>(ei);
    hist_kernel<<<(E + 255) / 256, 256>>>(ei, E);
    scan1_kernel<<<NBLK, 256>>>();
    scan2_kernel<<<1, 256>>>();
    scan3_kernel<<<NBLK, 256>>>();
    scatter_kernel<<<(E + 255) / 256, 256>>>(ei, E);

    // ---- join: conv1 needs both gemm1 and the CSR ----
    cudaStreamWaitEvent(0, evJoin, 0);

    conv1_kernel<<<(Nn * 16 + 255) / 256, 256>>>(b1, att1);

    dim3 g2(2, (Nn + 127) / 128);
    gemm_tc<<<g2, 256>>>(p_h1, Wl2, Wr2, p_xlr2, Nn, 64, 128);
    conv2_kernel<<<(Nn * 8 + 255) / 256, 256>>>(b2, att2, bat);

    final_kernel<<<1, 640>>>(Wlin, blin, out);
}